// round 4
// baseline (speedup 1.0000x reference)
#include <cuda_runtime.h>
#include <cuda_fp16.h>
#include <cstdint>

// ---------------- PTX helpers (family-agnostic: sm_80-level) ----------------

__device__ __forceinline__ uint32_t smem_u32(const void* p) {
    uint32_t a;
    asm("{ .reg .u64 t; cvta.to.shared.u64 t, %1; cvt.u32.u64 %0, t; }" : "=r"(a) : "l"(p));
    return a;
}

#define LDSM_X4(r0,r1,r2,r3,addr) \
    asm volatile("ldmatrix.sync.aligned.m8n8.x4.shared.b16 {%0,%1,%2,%3}, [%4];" \
        : "=r"(r0),"=r"(r1),"=r"(r2),"=r"(r3) : "r"(addr))

#define MMA_16816(c,a0,a1,a2,a3,b0,b1) \
    asm volatile("mma.sync.aligned.m16n8k16.row.col.f32.f16.f16.f32 " \
        "{%0,%1,%2,%3}, {%4,%5,%6,%7}, {%8,%9}, {%0,%1,%2,%3};" \
        : "+f"((c)[0]),"+f"((c)[1]),"+f"((c)[2]),"+f"((c)[3]) \
        : "r"(a0),"r"(a1),"r"(a2),"r"(a3),"r"(b0),"r"(b1))

#define CP_ASYNC16(dst,src) \
    asm volatile("cp.async.cg.shared.global [%0], [%1], 16;" :: "r"(dst),"l"(src) : "memory")
#define CP_COMMIT() asm volatile("cp.async.commit_group;" ::: "memory")
#define CP_WAIT0()  asm volatile("cp.async.wait_group 0;" ::: "memory")

#define LDS_V4(r0,r1,r2,r3,addr) \
    asm volatile("ld.shared.v4.u32 {%0,%1,%2,%3}, [%4];" \
        : "=r"(r0),"=r"(r1),"=r"(r2),"=r"(r3) : "r"(addr))

__device__ __forceinline__ uint32_t hmul2(uint32_t a, uint32_t b) {
    uint32_t d; asm("mul.rn.f16x2 %0, %1, %2;" : "=r"(d) : "r"(a), "r"(b)); return d;
}
__device__ __forceinline__ uint32_t packh2(float a, float b) {
    return (uint32_t)__half_as_ushort(__float2half_rn(a)) |
           ((uint32_t)__half_as_ushort(__float2half_rn(b)) << 16);
}
__device__ __forceinline__ uint32_t f2h2dup(float g) {
    uint32_t h = (uint32_t)__half_as_ushort(__float2half_rn(g));
    return h | (h << 16);
}

// ---------------- problem constants ----------------

static constexpr int TPB    = 256;
static constexpr int TILE_M = 128;   // tokens per CTA
static constexpr int TILE_N = 64;    // output features per CTA
static constexpr int DIM    = 128;
static constexpr int NEXP   = 8;

static constexpr int LDHB   = 272;   // 136 halves per row (conflict-free ldmatrix)
static constexpr int WSLICE = 64 * LDHB;   // 17408 B per expert slice
static constexpr int LDS_AG = 48;    // Ag/Bg row stride bytes (24 halves)

// smem layout (bytes)
static constexpr int OFF_XH   = 0;                       // 128 x 272B = 34816
static constexpr int OFF_WH   = 34816;                   // 8 x 17408  = 139264
static constexpr int OFF_G8   = 174080;                  // 8e x 2mg x 8key x 8j u32 = 4096
static constexpr int OFF_AG   = 178176;                  // 128 x 48B = 6144 (full gates f16, k-pad 16)
static constexpr int OFF_BG   = 184320;                  // 64 x 48B  = 3072 (b^T slice f16, k-pad 16)
static constexpr int OFF_GW   = 187392;                  // 4096 gate_W fp32
static constexpr int OFF_PART = 191488;                  // 8192 gating partials [256][8]
static constexpr int SMEM_BYTES = 199680;                // ~195 KB -> 1 CTA/SM

// W pre-converted to f16 (prepass), same linear order as fp32 W
__device__ __align__(16) unsigned char g_Wh[NEXP * DIM * DIM * 2];

__global__ void convert_w_kernel(const float* __restrict__ W) {
    int i = blockIdx.x * blockDim.x + threadIdx.x;     // 0..32767 float4s
    float4 v = ((const float4*)W)[i];
    ((uint2*)g_Wh)[i] = make_uint2(packh2(v.x, v.y), packh2(v.z, v.w));
}

// ---------------- main kernel ----------------

__global__ void __launch_bounds__(TPB, 1)
moe_f16_kernel(const float* __restrict__ x,
               const float* __restrict__ gW,
               const float* __restrict__ gb,
               const float* __restrict__ b,
               float* __restrict__ out)
{
    extern __shared__ char smem[];
    const uint32_t sb = smem_u32(smem);

    const int tid  = threadIdx.x;
    const int lane = tid & 31;
    const int wid  = tid >> 5;
    const int row  = tid & 127;          // token row within tile
    const int half = tid >> 7;           // K half for gating/X-load

    const int tile  = blockIdx.x >> 1;   // token tile
    const int nhalf = blockIdx.x & 1;    // which 64-wide output half
    const long tbase = (long)tile * TILE_M;

    // ---- issue cp.async for ALL 8 experts' W slices (overlaps everything) ----
    {
        #pragma unroll
        for (int it = 0; it < 32; it++) {
            const int c = tid + it * TPB;                // 8192 16B chunks
            const int e  = c >> 10;                      // 1024 chunks / expert
            const int r  = (c >> 4) & 63;                // row within slice
            const int c16 = c & 15;
            const uint32_t dst = sb + OFF_WH + (uint32_t)(e * WSLICE + r * LDHB + c16 * 16);
            const char* src = (const char*)g_Wh +
                ((size_t)e * DIM * DIM + (size_t)(nhalf * 64 + r) * DIM + c16 * 8) * 2;
            CP_ASYNC16(dst, src);
        }
        CP_COMMIT();
    }

    // ---- stage gate_W ----
    {
        float4* gws = (float4*)(smem + OFF_GW);
        gws[tid] = ((const float4*)gW)[tid];             // exactly 256 float4
    }

    // ---- stage Bg = b^T slice in f16, k-padded to 16 ----
    if (tid < TILE_N) {
        const int f = nhalf * 64 + tid;
        uint32_t* dst = (uint32_t*)(smem + OFF_BG + tid * LDS_AG);
        float bv[NEXP];
        #pragma unroll
        for (int e = 0; e < NEXP; e++) bv[e] = __ldg(b + e * DIM + f);
        dst[0] = packh2(bv[0], bv[1]);
        dst[1] = packh2(bv[2], bv[3]);
        dst[2] = packh2(bv[4], bv[5]);
        dst[3] = packh2(bv[6], bv[7]);
        dst[4] = 0; dst[5] = 0; dst[6] = 0; dst[7] = 0;
    }

    // ---- load X rows (fp32 regs) and stage f16 X tile ----
    float4 xv[16];
    {
        const float4* xg = (const float4*)(x + (tbase + row) * DIM + half * 64);
        #pragma unroll
        for (int i = 0; i < 16; i++) xv[i] = __ldg(xg + i);
        #pragma unroll
        for (int i = 0; i < 16; i++) {
            const int col = half * 64 + i * 4;
            uint32_t* d = (uint32_t*)(smem + OFF_XH + row * LDHB + col * 2);
            d[0] = packh2(xv[i].x, xv[i].y);
            d[1] = packh2(xv[i].z, xv[i].w);
        }
    }
    __syncthreads();

    // ---- gating partial dots ----
    {
        const float* gws = (const float*)(smem + OFF_GW);
        float* part = (float*)(smem + OFF_PART);
        #pragma unroll
        for (int e = 0; e < NEXP; e++) {
            const float4* ge = (const float4*)(gws + e * DIM) + half * 16;
            float s = 0.f;
            #pragma unroll
            for (int i = 0; i < 16; i++) {
                float4 g4 = ge[i];
                s += xv[i].x * g4.x + xv[i].y * g4.y + xv[i].z * g4.z + xv[i].w * g4.w;
            }
            part[(half * 128 + row) * NEXP + e] = s;
        }
    }
    __syncthreads();

    // ---- softmax + top-2 -> masked gates (g8 layout) + full gates (Ag) ----
    if (half == 0) {
        const float* part = (const float*)(smem + OFF_PART);
        float lg[NEXP];
        #pragma unroll
        for (int e = 0; e < NEXP; e++)
            lg[e] = part[row * NEXP + e] + part[(128 + row) * NEXP + e] + __ldg(gb + e);
        float m = lg[0];
        #pragma unroll
        for (int e = 1; e < NEXP; e++) m = fmaxf(m, lg[e]);
        float p[NEXP], s = 0.f;
        #pragma unroll
        for (int e = 0; e < NEXP; e++) { p[e] = expf(lg[e] - m); s += p[e]; }
        const float inv = 1.f / s;
        int i1 = 0;
        #pragma unroll
        for (int e = 1; e < NEXP; e++) if (lg[e] > lg[i1]) i1 = e;
        int i2 = (i1 == 0) ? 1 : 0;
        #pragma unroll
        for (int e = 0; e < NEXP; e++) if (e != i1 && lg[e] > lg[i2]) i2 = e;

        // g8[e][mgrp][key][j] = dup-h2 of masked gate for row mgrp*64 + j*8 + key
        const int mg  = row >> 6;
        const int j   = (row >> 3) & 7;
        const int key = row & 7;
        uint32_t* g8 = (uint32_t*)(smem + OFF_G8);
        float g[NEXP];
        #pragma unroll
        for (int e = 0; e < NEXP; e++) {
            g[e] = p[e] * inv;
            const float gmv = (e == i1 || e == i2) ? g[e] : 0.f;
            g8[((e * 2 + mg) * 8 + key) * 8 + j] = f2h2dup(gmv);
        }
        uint32_t* ag = (uint32_t*)(smem + OFF_AG + row * LDS_AG);
        ag[0] = packh2(g[0], g[1]);
        ag[1] = packh2(g[2], g[3]);
        ag[2] = packh2(g[4], g[5]);
        ag[3] = packh2(g[6], g[7]);
        ag[4] = 0; ag[5] = 0; ag[6] = 0; ag[7] = 0;
    }
    __syncthreads();

    // ---- warp tiling: 2(m) x 4(n); warp tile 64 x 16 ----
    const int mgrp = wid >> 2;                 // 0..1 -> rows mgrp*64..+63
    const int ngrp = wid & 3;                  // 0..3 -> cols ngrp*16..+15
    const int arow = lane & 15;
    const int acb  = (lane >> 4) * 8;          // A k-block (halves)
    const int brow = ((lane >> 4) & 1) * 8 + (lane & 7);
    const int bck  = ((lane >> 3) & 1) * 8;    // B k-block (halves)
    const int q    = lane >> 2;                // gate key for this lane

    float acc[4][2][4];
    #pragma unroll
    for (int t = 0; t < 4; t++)
        #pragma unroll
        for (int j = 0; j < 2; j++)
            #pragma unroll
            for (int k = 0; k < 4; k++) acc[t][j][k] = 0.f;

    // ---- bias GEMM step: D += gates_full @ b_slice ----
    {
        uint32_t b0, b1, b2, b3;
        uint32_t baddr = sb + OFF_BG + (uint32_t)((ngrp * 16 + brow) * LDS_AG + bck * 2);
        LDSM_X4(b0, b1, b2, b3, baddr);
        #pragma unroll
        for (int t = 0; t < 4; t++) {
            uint32_t a0, a1, a2, a3;
            uint32_t aaddr = sb + OFF_AG +
                (uint32_t)((mgrp * 64 + t * 16 + arow) * LDS_AG + acb * 2);
            LDSM_X4(a0, a1, a2, a3, aaddr);
            MMA_16816(acc[t][0], a0, a1, a2, a3, b0, b1);
            MMA_16816(acc[t][1], a0, a1, a2, a3, b2, b3);
        }
    }

    // W must be fully resident and visible before the main loop
    CP_WAIT0();
    __syncthreads();

    // ---- main loop: no syncs, no staging ----
    const uint32_t xbase = sb + OFF_XH + (uint32_t)((mgrp * 64 + arow) * LDHB + acb * 2);
    const uint32_t wbase = sb + OFF_WH + (uint32_t)((ngrp * 16 + brow) * LDHB + bck * 2);
    const uint32_t gbase = sb + OFF_G8 + (uint32_t)((mgrp * 8 + q) * 32);

    #pragma unroll
    for (int ks = 0; ks < 8; ks++) {
        uint32_t at[4][4];
        #pragma unroll
        for (int t = 0; t < 4; t++) {
            LDSM_X4(at[t][0], at[t][1], at[t][2], at[t][3],
                    xbase + (uint32_t)(t * 16 * LDHB + ks * 32));
        }
        #pragma unroll
        for (int e = 0; e < NEXP; e++) {
            uint32_t b0, b1, b2, b3;
            LDSM_X4(b0, b1, b2, b3, wbase + (uint32_t)(e * WSLICE + ks * 32));
            uint32_t gv[8];
            LDS_V4(gv[0], gv[1], gv[2], gv[3], gbase + (uint32_t)(e * 512));
            LDS_V4(gv[4], gv[5], gv[6], gv[7], gbase + (uint32_t)(e * 512 + 16));
            #pragma unroll
            for (int t = 0; t < 4; t++) {
                const uint32_t s0 = hmul2(at[t][0], gv[2 * t]);
                const uint32_t s1 = hmul2(at[t][1], gv[2 * t + 1]);
                const uint32_t s2 = hmul2(at[t][2], gv[2 * t]);
                const uint32_t s3 = hmul2(at[t][3], gv[2 * t + 1]);
                MMA_16816(acc[t][0], s0, s1, s2, s3, b0, b1);
                MMA_16816(acc[t][1], s0, s1, s2, s3, b2, b3);
            }
        }
    }

    // ---- store C fragments (bias already folded in) ----
    #pragma unroll
    for (int t = 0; t < 4; t++) {
        const long r0 = tbase + mgrp * 64 + t * 16 + (lane >> 2);
        const int colb = nhalf * 64 + ngrp * 16 + (lane & 3) * 2;
        #pragma unroll
        for (int j = 0; j < 2; j++) {
            const int col = colb + j * 8;
            *(float2*)(out + r0 * DIM + col)       = make_float2(acc[t][j][0], acc[t][j][1]);
            *(float2*)(out + (r0 + 8) * DIM + col) = make_float2(acc[t][j][2], acc[t][j][3]);
        }
    }
}

// ---------------- launch ----------------

extern "C" void kernel_launch(void* const* d_in, const int* in_sizes, int n_in,
                              void* d_out, int out_size)
{
    const float* x  = (const float*)d_in[0];
    const float* gW = (const float*)d_in[1];
    const float* gb = (const float*)d_in[2];
    const float* W  = (const float*)d_in[3];
    const float* b  = (const float*)d_in[4];
    float* out = (float*)d_out;

    const int rows = in_sizes[0] / DIM;          // 524288 tokens
    const int grid = (rows / TILE_M) * 2;        // 8192 CTAs (2 N-halves per tile)

    convert_w_kernel<<<NEXP * DIM * DIM / 4 / 256, 256>>>(W);

    cudaFuncSetAttribute(moe_f16_kernel,
                         cudaFuncAttributeMaxDynamicSharedMemorySize, SMEM_BYTES);
    moe_f16_kernel<<<grid, TPB, SMEM_BYTES>>>(x, gW, gb, b, out);
}

// round 5
// speedup vs baseline: 1.5089x; 1.5089x over previous
#include <cuda_runtime.h>
#include <cuda_fp16.h>
#include <cstdint>

// ---------------- PTX helpers (family-agnostic: sm_80-level) ----------------

__device__ __forceinline__ uint32_t smem_u32(const void* p) {
    uint32_t a;
    asm("{ .reg .u64 t; cvta.to.shared.u64 t, %1; cvt.u32.u64 %0, t; }" : "=r"(a) : "l"(p));
    return a;
}

#define LDSM_X4(r0,r1,r2,r3,addr) \
    asm volatile("ldmatrix.sync.aligned.m8n8.x4.shared.b16 {%0,%1,%2,%3}, [%4];" \
        : "=r"(r0),"=r"(r1),"=r"(r2),"=r"(r3) : "r"(addr))

#define MMA_16816(c,a0,a1,a2,a3,b0,b1) \
    asm volatile("mma.sync.aligned.m16n8k16.row.col.f32.f16.f16.f32 " \
        "{%0,%1,%2,%3}, {%4,%5,%6,%7}, {%8,%9}, {%0,%1,%2,%3};" \
        : "+f"((c)[0]),"+f"((c)[1]),"+f"((c)[2]),"+f"((c)[3]) \
        : "r"(a0),"r"(a1),"r"(a2),"r"(a3),"r"(b0),"r"(b1))

#define CP_ASYNC16(dst,src) \
    asm volatile("cp.async.cg.shared.global [%0], [%1], 16;" :: "r"(dst),"l"(src) : "memory")
#define CP_COMMIT() asm volatile("cp.async.commit_group;" ::: "memory")
#define CP_WAIT0()  asm volatile("cp.async.wait_group 0;" ::: "memory")

__device__ __forceinline__ uint32_t packh2(float a, float b) {
    return (uint32_t)__half_as_ushort(__float2half_rn(a)) |
           ((uint32_t)__half_as_ushort(__float2half_rn(b)) << 16);
}

// ---------------- problem constants ----------------

static constexpr int DIM   = 128;
static constexpr int NEXP  = 8;
static constexpr int NTOK  = 524288;
static constexpr int MAX_TILES = 4160;       // >= NTOK/128 + 28

static constexpr int LDHB  = 272;            // 136 halves per row (ldmatrix-friendly)

// main-kernel smem layout (bytes)
static constexpr int OFF_A0  = 0;            // 128 x 272  (g_a * x, k 0..127)
static constexpr int OFF_A1  = 34816;        // 128 x 272  (g_b * x)
static constexpr int OFF_B0  = 69632;        // 128 x 272  (W_a: n rows, k cols)
static constexpr int OFF_B1  = 104448;       // 128 x 272  (W_b)
static constexpr int OFF_AG  = 139264;       // 128 x 32   (full gates f16, k-pad 16)
static constexpr int OFF_BG  = 143360;       // 128 x 32   (b^T f16, k-pad 16)
static constexpr int OFF_TOK = 147456;       // 128 x 4    (token ids)
static constexpr int SMEM_MAIN = 147968;

// ---------------- device scratch (static: no allocations) ----------------

__device__ __align__(16) unsigned char g_Wh[NEXP * DIM * DIM * 2];  // W in f16
__device__ int    g_hist[64];
__device__ int    g_off[64];
__device__ int    g_ntiles[1];
__device__ int4   g_tiles[MAX_TILES];        // (start, count, e_a, e_b)
__device__ uint32_t g_pr[NTOK];              // p<<24 | rank
__device__ float2   g_g12[NTOK];             // (g_a, g_b)
__device__ uint4    g_gf[NTOK];              // 8 gates as f16
__device__ int      g_tok[NTOK];             // sorted token ids

// ---------------- kernel 0: zero hist ----------------

__global__ void zero_kernel() {
    g_hist[threadIdx.x] = 0;
}

// ---------------- kernel 1: W fp32 -> f16 ----------------

__global__ void convert_w_kernel(const float* __restrict__ W) {
    int i = blockIdx.x * blockDim.x + threadIdx.x;     // 32768 float4s
    float4 v = ((const float4*)W)[i];
    ((uint2*)g_Wh)[i] = make_uint2(packh2(v.x, v.y), packh2(v.z, v.w));
}

// ---------------- kernel 2: routing (gating + softmax + top-2) ----------------

__global__ void __launch_bounds__(256, 2)
routing_kernel(const float* __restrict__ x,
               const float* __restrict__ gW,
               const float* __restrict__ gb)
{
    __shared__ float gws[NEXP * DIM];
    __shared__ float part[256 * NEXP];

    const int tid  = threadIdx.x;
    const int row  = tid & 127;
    const int half = tid >> 7;
    const long tok0 = (long)blockIdx.x * 128;

    ((float4*)gws)[tid] = ((const float4*)gW)[tid];    // 256 float4 = 4 KB

    float4 xv[16];
    {
        const float4* xg = (const float4*)(x + (tok0 + row) * DIM + half * 64);
        #pragma unroll
        for (int i = 0; i < 16; i++) xv[i] = __ldg(xg + i);
    }
    __syncthreads();

    #pragma unroll
    for (int e = 0; e < NEXP; e++) {
        const float4* ge = (const float4*)(gws + e * DIM) + half * 16;
        float s = 0.f;
        #pragma unroll
        for (int i = 0; i < 16; i++) {
            float4 g4 = ge[i];
            s += xv[i].x * g4.x + xv[i].y * g4.y + xv[i].z * g4.z + xv[i].w * g4.w;
        }
        part[(half * 128 + row) * NEXP + e] = s;
    }
    __syncthreads();

    if (half == 0) {
        float lg[NEXP];
        #pragma unroll
        for (int e = 0; e < NEXP; e++)
            lg[e] = part[row * NEXP + e] + part[(128 + row) * NEXP + e] + __ldg(gb + e);
        float m = lg[0];
        #pragma unroll
        for (int e = 1; e < NEXP; e++) m = fmaxf(m, lg[e]);
        float p[NEXP], s = 0.f;
        #pragma unroll
        for (int e = 0; e < NEXP; e++) { p[e] = expf(lg[e] - m); s += p[e]; }
        const float inv = 1.f / s;
        float g[NEXP];
        #pragma unroll
        for (int e = 0; e < NEXP; e++) g[e] = p[e] * inv;

        int i1 = 0;
        #pragma unroll
        for (int e = 1; e < NEXP; e++) if (lg[e] > lg[i1]) i1 = e;
        int i2 = (i1 == 0) ? 1 : 0;
        #pragma unroll
        for (int e = 0; e < NEXP; e++) if (e != i1 && lg[e] > lg[i2]) i2 = e;

        const int a  = min(i1, i2);
        const int bb = max(i1, i2);
        const int pidx = a * 8 + bb;
        const long tok = tok0 + row;

        const int r = atomicAdd(&g_hist[pidx], 1);
        g_pr[tok]  = ((uint32_t)pidx << 24) | (uint32_t)r;
        g_g12[tok] = make_float2(g[a], g[bb]);
        g_gf[tok]  = make_uint4(packh2(g[0], g[1]), packh2(g[2], g[3]),
                                packh2(g[4], g[5]), packh2(g[6], g[7]));
    }
}

// ---------------- kernel 3: scan + tile table (1 block, 64 threads) ----------------

__global__ void scan_kernel() {
    __shared__ int soff[64], stoff[64];
    if (threadIdx.x == 0) {
        int s = 0, t = 0;
        for (int p = 0; p < 64; p++) {
            soff[p]  = s;
            stoff[p] = t;
            g_off[p] = s;
            const int c = g_hist[p];
            s += c;
            t += (c + 127) >> 7;
        }
        g_ntiles[0] = t;
    }
    __syncthreads();
    const int p = threadIdx.x;
    const int c = g_hist[p];
    const int a = p >> 3, bb = p & 7;
    const int base = soff[p];
    int tb = stoff[p];
    for (int s = 0; s < c; s += 128, tb++)
        g_tiles[tb] = make_int4(base + s, min(128, c - s), a, bb);
}

// ---------------- kernel 4: fill sorted token list ----------------

__global__ void fill_kernel() {
    const int tok = blockIdx.x * blockDim.x + threadIdx.x;
    const uint32_t v = g_pr[tok];
    const int p = v >> 24;
    const int r = v & 0xFFFFFF;
    g_tok[g_off[p] + r] = tok;
}

// ---------------- kernel 5: pair-group GEMM ----------------

__global__ void __launch_bounds__(512, 1)
moe_main_kernel(const float* __restrict__ x,
                const float* __restrict__ b,
                float* __restrict__ out)
{
    const int t = blockIdx.x;
    if (t >= __ldg(g_ntiles)) return;

    extern __shared__ char smem[];
    const uint32_t sb = smem_u32(smem);

    const int tid  = threadIdx.x;
    const int lane = tid & 31;
    const int wid  = tid >> 5;

    const int4 tl = __ldg(&g_tiles[t]);
    const int start = tl.x, count = tl.y, ea = tl.z, eb = tl.w;

    // ---- B staging: W_a, W_b (f16, 32 KB each) via cp.async ----
    {
        #pragma unroll
        for (int it = 0; it < 8; it++) {
            const int c = tid + it * 512;              // 4096 16B chunks
            const int e   = c >> 11;                   // 2048 chunks per expert
            const int r   = (c >> 4) & 127;
            const int c16 = c & 15;
            const int esel = e ? eb : ea;
            const uint32_t dst = sb + OFF_B0 + (uint32_t)(e * 34816 + r * LDHB + c16 * 16);
            const char* src = (const char*)g_Wh + ((size_t)esel * 32768 + r * 256 + c16 * 16);
            CP_ASYNC16(dst, src);
        }
        CP_COMMIT();
    }

    // ---- Bg = b^T for both... all 8 experts (bias term uses full gates) ----
    if (tid < DIM) {
        const int f = tid;
        float bv[NEXP];
        #pragma unroll
        for (int e = 0; e < NEXP; e++) bv[e] = __ldg(b + e * DIM + f);
        uint32_t* dst = (uint32_t*)(smem + OFF_BG + f * 32);
        dst[0] = packh2(bv[0], bv[1]);
        dst[1] = packh2(bv[2], bv[3]);
        dst[2] = packh2(bv[4], bv[5]);
        dst[3] = packh2(bv[6], bv[7]);
        dst[4] = 0; dst[5] = 0; dst[6] = 0; dst[7] = 0;
    }

    // ---- gather A rows: 4 threads per row, 32 floats each ----
    {
        const int row  = tid >> 2;
        const int part = tid & 3;
        const bool valid = row < count;
        int tok = 0;
        if (valid) tok = __ldg(&g_tok[start + row]);

        if (part == 0) {
            ((int*)(smem + OFF_TOK))[row] = tok;
            uint4 gf = valid ? __ldg(&g_gf[tok]) : make_uint4(0, 0, 0, 0);
            uint4* agr = (uint4*)(smem + OFF_AG + row * 32);
            agr[0] = gf;
            agr[1] = make_uint4(0, 0, 0, 0);
        }

        float ga = 0.f, gb2 = 0.f;
        if (valid) {
            float2 g12 = __ldg(&g_g12[tok]);
            ga = g12.x; gb2 = g12.y;
        }
        uint32_t* d0 = (uint32_t*)(smem + OFF_A0 + row * LDHB + part * 64);
        uint32_t* d1 = (uint32_t*)(smem + OFF_A1 + row * LDHB + part * 64);
        if (valid) {
            const float4* xg = (const float4*)(x + (long)tok * DIM + part * 32);
            #pragma unroll
            for (int i = 0; i < 8; i++) {
                float4 v = __ldg(xg + i);
                d0[2*i]   = packh2(v.x * ga,  v.y * ga);
                d0[2*i+1] = packh2(v.z * ga,  v.w * ga);
                d1[2*i]   = packh2(v.x * gb2, v.y * gb2);
                d1[2*i+1] = packh2(v.z * gb2, v.w * gb2);
            }
        } else {
            #pragma unroll
            for (int i = 0; i < 16; i++) { d0[i] = 0; d1[i] = 0; }
        }
    }
    __syncthreads();

    // ---- warp tiling: 4(m) x 4(n); warp tile 32 x 32 ----
    const int mgrp = wid >> 2;                   // 0..3 -> rows mgrp*32
    const int ngrp = wid & 3;                    // 0..3 -> cols ngrp*32
    const int arow = lane & 15;
    const int acb  = (lane >> 4) * 8;            // A k-block (halves)
    const int brow = ((lane >> 4) & 1) * 8 + (lane & 7);
    const int bck  = ((lane >> 3) & 1) * 8;      // B k-block (halves)

    float acc[2][4][4];
    #pragma unroll
    for (int t2 = 0; t2 < 2; t2++)
        #pragma unroll
        for (int j = 0; j < 4; j++)
            #pragma unroll
            for (int q = 0; q < 4; q++) acc[t2][j][q] = 0.f;

    // ---- bias MMA: D += gates_full @ b^T ----
    {
        uint32_t b0, b1, b2, b3, b4, b5, b6, b7;
        LDSM_X4(b0, b1, b2, b3, sb + OFF_BG + (uint32_t)((ngrp * 32 + brow) * 32 + bck * 2));
        LDSM_X4(b4, b5, b6, b7, sb + OFF_BG + (uint32_t)((ngrp * 32 + 16 + brow) * 32 + bck * 2));
        #pragma unroll
        for (int t2 = 0; t2 < 2; t2++) {
            uint32_t a0, a1, a2, a3;
            LDSM_X4(a0, a1, a2, a3,
                    sb + OFF_AG + (uint32_t)((mgrp * 32 + t2 * 16 + arow) * 32 + acb * 2));
            MMA_16816(acc[t2][0], a0, a1, a2, a3, b0, b1);
            MMA_16816(acc[t2][1], a0, a1, a2, a3, b2, b3);
            MMA_16816(acc[t2][2], a0, a1, a2, a3, b4, b5);
            MMA_16816(acc[t2][3], a0, a1, a2, a3, b6, b7);
        }
    }

    CP_WAIT0();
    __syncthreads();

    // ---- main loop: K=256 (two phases of 128), no syncs ----
    #pragma unroll
    for (int ph = 0; ph < 2; ph++) {
        const uint32_t abase = sb + (ph ? OFF_A1 : OFF_A0) +
                               (uint32_t)((mgrp * 32 + arow) * LDHB + acb * 2);
        const uint32_t bbase = sb + (ph ? OFF_B1 : OFF_B0) +
                               (uint32_t)((ngrp * 32 + brow) * LDHB + bck * 2);
        #pragma unroll
        for (int ks = 0; ks < 8; ks++) {
            uint32_t a0[4], a1[4];
            LDSM_X4(a0[0], a0[1], a0[2], a0[3], abase + (uint32_t)(ks * 32));
            LDSM_X4(a1[0], a1[1], a1[2], a1[3], abase + (uint32_t)(16 * LDHB + ks * 32));
            uint32_t b0, b1, b2, b3, b4, b5, b6, b7;
            LDSM_X4(b0, b1, b2, b3, bbase + (uint32_t)(ks * 32));
            LDSM_X4(b4, b5, b6, b7, bbase + (uint32_t)(16 * LDHB + ks * 32));
            MMA_16816(acc[0][0], a0[0], a0[1], a0[2], a0[3], b0, b1);
            MMA_16816(acc[0][1], a0[0], a0[1], a0[2], a0[3], b2, b3);
            MMA_16816(acc[0][2], a0[0], a0[1], a0[2], a0[3], b4, b5);
            MMA_16816(acc[0][3], a0[0], a0[1], a0[2], a0[3], b6, b7);
            MMA_16816(acc[1][0], a1[0], a1[1], a1[2], a1[3], b0, b1);
            MMA_16816(acc[1][1], a1[0], a1[1], a1[2], a1[3], b2, b3);
            MMA_16816(acc[1][2], a1[0], a1[1], a1[2], a1[3], b4, b5);
            MMA_16816(acc[1][3], a1[0], a1[1], a1[2], a1[3], b6, b7);
        }
    }

    // ---- scatter stores (one write per token row; bias folded in) ----
    {
        const int* stok = (const int*)(smem + OFF_TOK);
        #pragma unroll
        for (int t2 = 0; t2 < 2; t2++) {
            const int lr = mgrp * 32 + t2 * 16 + (lane >> 2);
            const bool ok0 = lr < count;
            const bool ok1 = (lr + 8) < count;
            const long tok0 = ok0 ? stok[lr] : 0;
            const long tok1 = ok1 ? stok[lr + 8] : 0;
            #pragma unroll
            for (int j = 0; j < 4; j++) {
                const int col = ngrp * 32 + j * 8 + (lane & 3) * 2;
                if (ok0) *(float2*)(out + tok0 * DIM + col) =
                    make_float2(acc[t2][j][0], acc[t2][j][1]);
                if (ok1) *(float2*)(out + tok1 * DIM + col) =
                    make_float2(acc[t2][j][2], acc[t2][j][3]);
            }
        }
    }
}

// ---------------- launch ----------------

extern "C" void kernel_launch(void* const* d_in, const int* in_sizes, int n_in,
                              void* d_out, int out_size)
{
    const float* x  = (const float*)d_in[0];
    const float* gW = (const float*)d_in[1];
    const float* gb = (const float*)d_in[2];
    const float* W  = (const float*)d_in[3];
    const float* b  = (const float*)d_in[4];
    float* out = (float*)d_out;

    zero_kernel<<<1, 64>>>();
    convert_w_kernel<<<NEXP * DIM * DIM / 4 / 256, 256>>>(W);
    routing_kernel<<<NTOK / 128, 256>>>(x, gW, gb);
    scan_kernel<<<1, 64>>>();
    fill_kernel<<<NTOK / 256, 256>>>();

    cudaFuncSetAttribute(moe_main_kernel,
                         cudaFuncAttributeMaxDynamicSharedMemorySize, SMEM_MAIN);
    moe_main_kernel<<<MAX_TILES, 512, SMEM_MAIN>>>(x, b, out);
}

// round 6
// speedup vs baseline: 1.5093x; 1.0003x over previous
#include <cuda_runtime.h>
#include <cuda_fp16.h>
#include <cstdint>

// ---------------- PTX helpers (family-agnostic: sm_80-level) ----------------

__device__ __forceinline__ uint32_t smem_u32(const void* p) {
    uint32_t a;
    asm("{ .reg .u64 t; cvta.to.shared.u64 t, %1; cvt.u32.u64 %0, t; }" : "=r"(a) : "l"(p));
    return a;
}

#define LDSM_X4(r0,r1,r2,r3,addr) \
    asm volatile("ldmatrix.sync.aligned.m8n8.x4.shared.b16 {%0,%1,%2,%3}, [%4];" \
        : "=r"(r0),"=r"(r1),"=r"(r2),"=r"(r3) : "r"(addr))

#define MMA_16816(c,a0,a1,a2,a3,b0,b1) \
    asm volatile("mma.sync.aligned.m16n8k16.row.col.f32.f16.f16.f32 " \
        "{%0,%1,%2,%3}, {%4,%5,%6,%7}, {%8,%9}, {%0,%1,%2,%3};" \
        : "+f"((c)[0]),"+f"((c)[1]),"+f"((c)[2]),"+f"((c)[3]) \
        : "r"(a0),"r"(a1),"r"(a2),"r"(a3),"r"(b0),"r"(b1))

#define CP_ASYNC16(dst,src) \
    asm volatile("cp.async.cg.shared.global [%0], [%1], 16;" :: "r"(dst),"l"(src) : "memory")
#define CP_COMMIT() asm volatile("cp.async.commit_group;" ::: "memory")
#define CP_WAIT0()  asm volatile("cp.async.wait_group 0;" ::: "memory")

__device__ __forceinline__ uint32_t packh2(float a, float b) {
    return (uint32_t)__half_as_ushort(__float2half_rn(a)) |
           ((uint32_t)__half_as_ushort(__float2half_rn(b)) << 16);
}

// ---------------- problem constants ----------------

static constexpr int DIM   = 128;
static constexpr int NEXP  = 8;
static constexpr int NTOK  = 524288;
static constexpr int MAX_TILES = 4160;

static constexpr int LDHB  = 272;            // 136 halves per row (ldmatrix-friendly)
static constexpr int LDOUT = 132;            // out-staging row stride (floats)

// main-kernel smem layout (bytes)
static constexpr int OFF_A   = 0;            // 128 x 272  (x f16)   [reused by out tile]
static constexpr int OFF_B0  = 34816;        // 128 x 272  (W_a)     [reused by out tile]
static constexpr int OFF_B1  = 69632;        // 128 x 272  (W_b)
static constexpr int OFF_AG  = 104448;       // 128 x 32   (full gates f16, k-pad 16)
static constexpr int OFF_BG  = 108544;       // 128 x 32   (b^T f16, k-pad 16)
static constexpr int OFF_G12 = 112640;       // 128 x 8    (ga, gb fp32)
static constexpr int OFF_TOK = 113664;       // 128 x 4    (token ids)
static constexpr int SMEM_MAIN = 114176;
// out staging reuses [0 .. 128*132*4 = 67584)

// ---------------- device scratch (static: no allocations) ----------------

__device__ __align__(16) unsigned char g_Wh[NEXP * DIM * DIM * 2];  // W in f16
__device__ int    g_hist[64];
__device__ int    g_off[64];
__device__ int    g_ntiles[1];
__device__ int4   g_tiles[MAX_TILES];        // (start, count, e_a, e_b)
__device__ uint32_t g_pr[NTOK];              // pair<<24 | rank
__device__ float2   g_g12[NTOK];             // (g_a, g_b)
__device__ uint4    g_gf[NTOK];              // 8 gates as f16
__device__ int      g_tok[NTOK];             // grouped token ids

// ---------------- kernel 1: W fp32 -> f16 (+ zero hist) ----------------

__global__ void convert_w_kernel(const float* __restrict__ W) {
    if (blockIdx.x == 0 && threadIdx.x < 64) g_hist[threadIdx.x] = 0;
    int i = blockIdx.x * blockDim.x + threadIdx.x;     // 32768 float4s
    float4 v = ((const float4*)W)[i];
    ((uint2*)g_Wh)[i] = make_uint2(packh2(v.x, v.y), packh2(v.z, v.w));
}

// ---------------- kernel 2: routing (gating + softmax + top-2) ----------------

__global__ void __launch_bounds__(256, 2)
routing_kernel(const float* __restrict__ x,
               const float* __restrict__ gW,
               const float* __restrict__ gb)
{
    __shared__ float gws[NEXP * DIM];
    __shared__ float part[256 * NEXP];

    const int tid  = threadIdx.x;
    const int row  = tid & 127;
    const int half = tid >> 7;
    const long tok0 = (long)blockIdx.x * 128;

    ((float4*)gws)[tid] = ((const float4*)gW)[tid];

    float4 xv[16];
    {
        const float4* xg = (const float4*)(x + (tok0 + row) * DIM + half * 64);
        #pragma unroll
        for (int i = 0; i < 16; i++) xv[i] = __ldg(xg + i);
    }
    __syncthreads();

    #pragma unroll
    for (int e = 0; e < NEXP; e++) {
        const float4* ge = (const float4*)(gws + e * DIM) + half * 16;
        float s = 0.f;
        #pragma unroll
        for (int i = 0; i < 16; i++) {
            float4 g4 = ge[i];
            s += xv[i].x * g4.x + xv[i].y * g4.y + xv[i].z * g4.z + xv[i].w * g4.w;
        }
        part[(half * 128 + row) * NEXP + e] = s;
    }
    __syncthreads();

    if (half == 0) {
        float lg[NEXP];
        #pragma unroll
        for (int e = 0; e < NEXP; e++)
            lg[e] = part[row * NEXP + e] + part[(128 + row) * NEXP + e] + __ldg(gb + e);
        float m = lg[0];
        #pragma unroll
        for (int e = 1; e < NEXP; e++) m = fmaxf(m, lg[e]);
        float p[NEXP], s = 0.f;
        #pragma unroll
        for (int e = 0; e < NEXP; e++) { p[e] = expf(lg[e] - m); s += p[e]; }
        const float inv = 1.f / s;
        float g[NEXP];
        #pragma unroll
        for (int e = 0; e < NEXP; e++) g[e] = p[e] * inv;

        int i1 = 0;
        #pragma unroll
        for (int e = 1; e < NEXP; e++) if (lg[e] > lg[i1]) i1 = e;
        int i2 = (i1 == 0) ? 1 : 0;
        #pragma unroll
        for (int e = 0; e < NEXP; e++) if (e != i1 && lg[e] > lg[i2]) i2 = e;

        const int a  = min(i1, i2);
        const int bb = max(i1, i2);
        const int pidx = a * 8 + bb;
        const long tok = tok0 + row;

        const int r = atomicAdd(&g_hist[pidx], 1);
        g_pr[tok]  = ((uint32_t)pidx << 24) | (uint32_t)r;
        g_g12[tok] = make_float2(g[a], g[bb]);
        g_gf[tok]  = make_uint4(packh2(g[0], g[1]), packh2(g[2], g[3]),
                                packh2(g[4], g[5]), packh2(g[6], g[7]));
    }
}

// ---------------- kernel 3: parallel scan + tile table ----------------

__global__ void scan_kernel() {
    __shared__ int sc[64], st[64];
    const int p = threadIdx.x;
    const int c  = g_hist[p];
    const int nt = (c + 127) >> 7;
    sc[p] = c; st[p] = nt;
    __syncthreads();
    #pragma unroll
    for (int d = 1; d < 64; d <<= 1) {
        int vc = 0, vt = 0;
        if (p >= d) { vc = sc[p - d]; vt = st[p - d]; }
        __syncthreads();
        sc[p] += vc; st[p] += vt;
        __syncthreads();
    }
    const int base = sc[p] - c;          // exclusive token offset
    int tb = st[p] - nt;                 // exclusive tile offset
    g_off[p] = base;
    if (p == 63) g_ntiles[0] = st[63];
    const int a = p >> 3, bb = p & 7;
    for (int s = 0; s < c; s += 128, tb++)
        g_tiles[tb] = make_int4(base + s, min(128, c - s), a, bb);
}

// ---------------- kernel 4: fill grouped token list ----------------

__global__ void fill_kernel() {
    const int tok = blockIdx.x * blockDim.x + threadIdx.x;
    const uint32_t v = g_pr[tok];
    g_tok[g_off[v >> 24] + (v & 0xFFFFFF)] = tok;
}

// ---------------- kernel 5: pair-group GEMM ----------------

__global__ void __launch_bounds__(512, 1)
moe_main_kernel(const float* __restrict__ x,
                const float* __restrict__ b,
                float* __restrict__ out)
{
    const int t = blockIdx.x;
    if (t >= __ldg(g_ntiles)) return;

    extern __shared__ char smem[];
    const uint32_t sb = smem_u32(smem);

    const int tid  = threadIdx.x;
    const int lane = tid & 31;
    const int wid  = tid >> 5;

    const int4 tl = __ldg(&g_tiles[t]);
    const int start = tl.x, count = tl.y, ea = tl.z, eb = tl.w;

    // ---- B staging: W_a, W_b (f16, 32 KB each) via cp.async ----
    {
        #pragma unroll
        for (int it = 0; it < 8; it++) {
            const int c = tid + it * 512;              // 4096 16B chunks
            const int e   = c >> 11;                   // 2048 per expert
            const int r   = (c >> 4) & 127;
            const int c16 = c & 15;
            const int esel = e ? eb : ea;
            const uint32_t dst = sb + OFF_B0 + (uint32_t)(e * 34816 + r * LDHB + c16 * 16);
            const char* src = (const char*)g_Wh + ((size_t)esel * 32768 + r * 256 + c16 * 16);
            CP_ASYNC16(dst, src);
        }
        CP_COMMIT();
    }

    // ---- Bg = b^T (all 8 experts) in f16, k-pad 16 ----
    if (tid < DIM) {
        float bv[NEXP];
        #pragma unroll
        for (int e = 0; e < NEXP; e++) bv[e] = __ldg(b + e * DIM + tid);
        uint32_t* dst = (uint32_t*)(smem + OFF_BG + tid * 32);
        dst[0] = packh2(bv[0], bv[1]);
        dst[1] = packh2(bv[2], bv[3]);
        dst[2] = packh2(bv[4], bv[5]);
        dst[3] = packh2(bv[6], bv[7]);
        dst[4] = 0; dst[5] = 0; dst[6] = 0; dst[7] = 0;
    }

    // ---- gather A rows (unscaled x -> f16): 4 threads per row ----
    {
        const int row  = tid >> 2;
        const int part = tid & 3;
        const bool valid = row < count;
        int tok = 0;
        if (valid) tok = __ldg(&g_tok[start + row]);

        if (part == 0) {
            ((int*)(smem + OFF_TOK))[row] = tok;
            ((float2*)(smem + OFF_G12))[row] = valid ? __ldg(&g_g12[tok]) : make_float2(0.f, 0.f);
            uint4 gf = valid ? __ldg(&g_gf[tok]) : make_uint4(0, 0, 0, 0);
            uint4* agr = (uint4*)(smem + OFF_AG + row * 32);
            agr[0] = gf;
            agr[1] = make_uint4(0, 0, 0, 0);
        }

        uint4* d = (uint4*)(smem + OFF_A + row * LDHB + part * 64);
        if (valid) {
            const float4* xg = (const float4*)(x + (long)tok * DIM + part * 32);
            #pragma unroll
            for (int i = 0; i < 4; i++) {
                float4 v0 = __ldg(xg + 2 * i);
                float4 v1 = __ldg(xg + 2 * i + 1);
                d[i] = make_uint4(packh2(v0.x, v0.y), packh2(v0.z, v0.w),
                                  packh2(v1.x, v1.y), packh2(v1.z, v1.w));
            }
        } else {
            #pragma unroll
            for (int i = 0; i < 4; i++) d[i] = make_uint4(0, 0, 0, 0);
        }
    }

    CP_WAIT0();
    __syncthreads();

    // ---- warp tiling: 4(m) x 4(n); warp tile 32 x 32; dual accumulators ----
    const int mgrp = wid >> 2;
    const int ngrp = wid & 3;
    const int arow = lane & 15;
    const int acb  = (lane >> 4) * 8;
    const int brow = ((lane >> 4) & 1) * 8 + (lane & 7);
    const int bck  = ((lane >> 3) & 1) * 8;

    float accA[2][4][4], accB[2][4][4];
    #pragma unroll
    for (int t2 = 0; t2 < 2; t2++)
        #pragma unroll
        for (int j = 0; j < 4; j++)
            #pragma unroll
            for (int q = 0; q < 4; q++) { accA[t2][j][q] = 0.f; accB[t2][j][q] = 0.f; }

    const uint32_t abase  = sb + OFF_A  + (uint32_t)((mgrp * 32 + arow) * LDHB + acb * 2);
    const uint32_t b0base = sb + OFF_B0 + (uint32_t)((ngrp * 32 + brow) * LDHB + bck * 2);
    const uint32_t b1base = sb + OFF_B1 + (uint32_t)((ngrp * 32 + brow) * LDHB + bck * 2);

    #pragma unroll
    for (int ks = 0; ks < 8; ks++) {
        uint32_t a0[4], a1[4];
        LDSM_X4(a0[0], a0[1], a0[2], a0[3], abase + (uint32_t)(ks * 32));
        LDSM_X4(a1[0], a1[1], a1[2], a1[3], abase + (uint32_t)(16 * LDHB + ks * 32));
        uint32_t p0, p1, p2, p3, p4, p5, p6, p7;
        LDSM_X4(p0, p1, p2, p3, b0base + (uint32_t)(ks * 32));
        LDSM_X4(p4, p5, p6, p7, b0base + (uint32_t)(16 * LDHB + ks * 32));
        MMA_16816(accA[0][0], a0[0], a0[1], a0[2], a0[3], p0, p1);
        MMA_16816(accA[0][1], a0[0], a0[1], a0[2], a0[3], p2, p3);
        MMA_16816(accA[0][2], a0[0], a0[1], a0[2], a0[3], p4, p5);
        MMA_16816(accA[0][3], a0[0], a0[1], a0[2], a0[3], p6, p7);
        MMA_16816(accA[1][0], a1[0], a1[1], a1[2], a1[3], p0, p1);
        MMA_16816(accA[1][1], a1[0], a1[1], a1[2], a1[3], p2, p3);
        MMA_16816(accA[1][2], a1[0], a1[1], a1[2], a1[3], p4, p5);
        MMA_16816(accA[1][3], a1[0], a1[1], a1[2], a1[3], p6, p7);
        uint32_t q0, q1, q2, q3, q4, q5, q6, q7;
        LDSM_X4(q0, q1, q2, q3, b1base + (uint32_t)(ks * 32));
        LDSM_X4(q4, q5, q6, q7, b1base + (uint32_t)(16 * LDHB + ks * 32));
        MMA_16816(accB[0][0], a0[0], a0[1], a0[2], a0[3], q0, q1);
        MMA_16816(accB[0][1], a0[0], a0[1], a0[2], a0[3], q2, q3);
        MMA_16816(accB[0][2], a0[0], a0[1], a0[2], a0[3], q4, q5);
        MMA_16816(accB[0][3], a0[0], a0[1], a0[2], a0[3], q6, q7);
        MMA_16816(accB[1][0], a1[0], a1[1], a1[2], a1[3], q0, q1);
        MMA_16816(accB[1][1], a1[0], a1[1], a1[2], a1[3], q2, q3);
        MMA_16816(accB[1][2], a1[0], a1[1], a1[2], a1[3], q4, q5);
        MMA_16816(accB[1][3], a1[0], a1[1], a1[2], a1[3], q6, q7);
    }

    // ---- epilogue part 1: combine accA = ga*accA + gb*accB (per-row gates) ----
    const float2* g12s = (const float2*)(smem + OFF_G12);
    #pragma unroll
    for (int t2 = 0; t2 < 2; t2++) {
        const int rlo = mgrp * 32 + t2 * 16 + (lane >> 2);
        const float2 glo = g12s[rlo];
        const float2 ghi = g12s[rlo + 8];
        #pragma unroll
        for (int j = 0; j < 4; j++) {
            accA[t2][j][0] = glo.x * accA[t2][j][0] + glo.y * accB[t2][j][0];
            accA[t2][j][1] = glo.x * accA[t2][j][1] + glo.y * accB[t2][j][1];
            accA[t2][j][2] = ghi.x * accA[t2][j][2] + ghi.y * accB[t2][j][2];
            accA[t2][j][3] = ghi.x * accA[t2][j][3] + ghi.y * accB[t2][j][3];
        }
    }

    // ---- epilogue part 2: bias MMA (gates_full @ b^T) accumulates into accA ----
    {
        uint32_t b0, b1, b2, b3, b4, b5, b6, b7;
        LDSM_X4(b0, b1, b2, b3, sb + OFF_BG + (uint32_t)((ngrp * 32 + brow) * 32 + bck * 2));
        LDSM_X4(b4, b5, b6, b7, sb + OFF_BG + (uint32_t)((ngrp * 32 + 16 + brow) * 32 + bck * 2));
        #pragma unroll
        for (int t2 = 0; t2 < 2; t2++) {
            uint32_t a0, a1, a2, a3;
            LDSM_X4(a0, a1, a2, a3,
                    sb + OFF_AG + (uint32_t)((mgrp * 32 + t2 * 16 + arow) * 32 + acb * 2));
            MMA_16816(accA[t2][0], a0, a1, a2, a3, b0, b1);
            MMA_16816(accA[t2][1], a0, a1, a2, a3, b2, b3);
            MMA_16816(accA[t2][2], a0, a1, a2, a3, b4, b5);
            MMA_16816(accA[t2][3], a0, a1, a2, a3, b6, b7);
        }
    }

    // ---- epilogue part 3: stage out tile in smem (reuse A/B region) ----
    __syncthreads();       // everyone done reading A/B smem
    {
        float* osm = (float*)smem;     // [128][LDOUT]
        #pragma unroll
        for (int t2 = 0; t2 < 2; t2++) {
            const int rlo = mgrp * 32 + t2 * 16 + (lane >> 2);
            #pragma unroll
            for (int j = 0; j < 4; j++) {
                const int col = ngrp * 32 + j * 8 + (lane & 3) * 2;
                *(float2*)(osm + rlo * LDOUT + col) =
                    make_float2(accA[t2][j][0], accA[t2][j][1]);
                *(float2*)(osm + (rlo + 8) * LDOUT + col) =
                    make_float2(accA[t2][j][2], accA[t2][j][3]);
            }
        }
    }
    __syncthreads();

    // ---- epilogue part 4: coalesced row writes (512B contiguous per token) ----
    {
        const int row  = tid >> 2;
        const int part = tid & 3;
        if (row < count) {
            const long tok = ((const int*)(smem + OFF_TOK))[row];
            const float* osr = (const float*)smem + row * LDOUT;
            float4* og = (float4*)(out + tok * DIM);
            #pragma unroll
            for (int i = 0; i < 8; i++) {
                const int f4 = i * 4 + part;           // lanes of a quad -> 64B contiguous
                og[f4] = *(const float4*)(osr + f4 * 4);
            }
        }
    }
}

// ---------------- launch ----------------

extern "C" void kernel_launch(void* const* d_in, const int* in_sizes, int n_in,
                              void* d_out, int out_size)
{
    const float* x  = (const float*)d_in[0];
    const float* gW = (const float*)d_in[1];
    const float* gb = (const float*)d_in[2];
    const float* W  = (const float*)d_in[3];
    const float* b  = (const float*)d_in[4];
    float* out = (float*)d_out;

    convert_w_kernel<<<NEXP * DIM * DIM / 4 / 256, 256>>>(W);
    routing_kernel<<<NTOK / 128, 256>>>(x, gW, gb);
    scan_kernel<<<1, 64>>>();
    fill_kernel<<<NTOK / 256, 256>>>();

    cudaFuncSetAttribute(moe_main_kernel,
                         cudaFuncAttributeMaxDynamicSharedMemorySize, SMEM_MAIN);
    moe_main_kernel<<<MAX_TILES, 512, SMEM_MAIN>>>(x, b, out);
}

// round 7
// speedup vs baseline: 1.9509x; 1.2925x over previous
#include <cuda_runtime.h>
#include <cuda_fp16.h>
#include <cstdint>

// ---------------- PTX helpers (family-agnostic: sm_80-level) ----------------

__device__ __forceinline__ uint32_t smem_u32(const void* p) {
    uint32_t a;
    asm("{ .reg .u64 t; cvta.to.shared.u64 t, %1; cvt.u32.u64 %0, t; }" : "=r"(a) : "l"(p));
    return a;
}

#define LDSM_X4(r0,r1,r2,r3,addr) \
    asm volatile("ldmatrix.sync.aligned.m8n8.x4.shared.b16 {%0,%1,%2,%3}, [%4];" \
        : "=r"(r0),"=r"(r1),"=r"(r2),"=r"(r3) : "r"(addr))

#define MMA_16816(c,a0,a1,a2,a3,b0,b1) \
    asm volatile("mma.sync.aligned.m16n8k16.row.col.f32.f16.f16.f32 " \
        "{%0,%1,%2,%3}, {%4,%5,%6,%7}, {%8,%9}, {%0,%1,%2,%3};" \
        : "+f"((c)[0]),"+f"((c)[1]),"+f"((c)[2]),"+f"((c)[3]) \
        : "r"(a0),"r"(a1),"r"(a2),"r"(a3),"r"(b0),"r"(b1))

#define CP_ASYNC16(dst,src) \
    asm volatile("cp.async.cg.shared.global [%0], [%1], 16;" :: "r"(dst),"l"(src) : "memory")
#define CP_ASYNC16Z(dst,src,sz) \
    asm volatile("cp.async.cg.shared.global [%0], [%1], 16, %2;" :: "r"(dst),"l"(src),"r"(sz) : "memory")
#define CP_ASYNC8Z(dst,src,sz) \
    asm volatile("cp.async.ca.shared.global [%0], [%1], 8, %2;" :: "r"(dst),"l"(src),"r"(sz) : "memory")
#define CP_COMMIT() asm volatile("cp.async.commit_group;" ::: "memory")
#define CP_WAIT1()  asm volatile("cp.async.wait_group 1;" ::: "memory")

__device__ __forceinline__ uint32_t packh2(float a, float b) {
    return (uint32_t)__half_as_ushort(__float2half_rn(a)) |
           ((uint32_t)__half_as_ushort(__float2half_rn(b)) << 16);
}

// ---------------- problem constants ----------------

static constexpr int DIM   = 128;
static constexpr int NEXP  = 8;
static constexpr int NTOK  = 524288;
static constexpr int MAX_TILES = 4160;

// main-kernel smem layout (bytes); A/B rows are 256B, XOR-swizzled chunks
static constexpr int OFF_A   = 0;        // 2 x 32768  (x f16, 128 rows x 256B)
static constexpr int OFF_B   = 65536;    // 2 x 65536  (Wa 32KB + Wb 32KB per buf)
static constexpr int OFF_AG  = 196608;   // 2 x 4096   (full gates f16, 32B rows, k-pad)
static constexpr int OFF_G12 = 204800;   // 2 x 1024   (ga,gb fp32)
static constexpr int OFF_TK  = 206848;   // 2 x 512    (token ids)
static constexpr int OFF_BG  = 207872;   // 4096       (b^T f16, 32B rows, k-pad)
static constexpr int SMEM_MAIN = 211968;

// ---------------- device scratch (static: no allocations) ----------------

__device__ __align__(16) unsigned char g_Wh[NEXP * DIM * DIM * 2];   // W in f16
__device__ __align__(16) unsigned char g_xh[(size_t)NTOK * DIM * 2]; // x in f16 (128 MB)
__device__ int    g_hist[64];
__device__ int    g_off[64];
__device__ int    g_ntiles[1];
__device__ int4   g_tiles[MAX_TILES];    // (start, count, e_a, e_b)
__device__ uint32_t g_pr[NTOK];          // pair<<24 | rank
__device__ float2   g_g12[NTOK];         // (g_a, g_b)
__device__ uint4    g_gf[NTOK];          // 8 gates as f16
__device__ int      g_tok[NTOK];         // grouped token ids

// ---------------- kernel 1: W fp32 -> f16 (+ zero hist) ----------------

__global__ void convert_w_kernel(const float* __restrict__ W) {
    if (blockIdx.x == 0 && threadIdx.x < 64) g_hist[threadIdx.x] = 0;
    int i = blockIdx.x * blockDim.x + threadIdx.x;     // 32768 float4s
    float4 v = ((const float4*)W)[i];
    ((uint2*)g_Wh)[i] = make_uint2(packh2(v.x, v.y), packh2(v.z, v.w));
}

// ---------------- kernel 2: routing (gating + softmax + top-2 + x->f16) ----------------

__global__ void __launch_bounds__(256, 2)
routing_kernel(const float* __restrict__ x,
               const float* __restrict__ gW,
               const float* __restrict__ gb)
{
    __shared__ float gws[NEXP * DIM];          // 4 KB
    __shared__ float part[256 * NEXP];         // 8 KB
    __shared__ char  xstage[128 * 256];        // 32 KB (f16 rows, swizzled chunks)

    const int tid  = threadIdx.x;
    const int row  = tid & 127;
    const int half = tid >> 7;
    const long tok0 = (long)blockIdx.x * 128;

    ((float4*)gws)[tid] = ((const float4*)gW)[tid];

    float4 xv[16];
    {
        const float4* xg = (const float4*)(x + (tok0 + row) * DIM + half * 64);
        #pragma unroll
        for (int i = 0; i < 16; i++) xv[i] = __ldg(xg + i);
    }

    // stage f16 row halves into swizzled xstage
    {
        const int x7 = row & 7;
        #pragma unroll
        for (int j = 0; j < 8; j++) {
            uint4 u = make_uint4(packh2(xv[2*j].x,   xv[2*j].y),
                                 packh2(xv[2*j].z,   xv[2*j].w),
                                 packh2(xv[2*j+1].x, xv[2*j+1].y),
                                 packh2(xv[2*j+1].z, xv[2*j+1].w));
            const int c16 = half * 8 + j;
            *(uint4*)(xstage + row * 256 + ((c16 ^ x7) << 4)) = u;
        }
    }
    __syncthreads();

    // coalesced xh store (reads de-swizzled)
    {
        uint4* xg = (uint4*)(g_xh + (size_t)tok0 * 256);
        #pragma unroll
        for (int it = 0; it < 8; it++) {
            const int j  = tid + it * 256;       // 2048 chunks
            const int r  = j >> 4;
            const int c16 = j & 15;
            xg[j] = *(const uint4*)(xstage + r * 256 + ((c16 ^ (r & 7)) << 4));
        }
    }

    // gating partial dots
    #pragma unroll
    for (int e = 0; e < NEXP; e++) {
        const float4* ge = (const float4*)(gws + e * DIM) + half * 16;
        float s = 0.f;
        #pragma unroll
        for (int i = 0; i < 16; i++) {
            float4 g4 = ge[i];
            s += xv[i].x * g4.x + xv[i].y * g4.y + xv[i].z * g4.z + xv[i].w * g4.w;
        }
        part[(half * 128 + row) * NEXP + e] = s;
    }
    __syncthreads();

    if (half == 0) {
        float lg[NEXP];
        #pragma unroll
        for (int e = 0; e < NEXP; e++)
            lg[e] = part[row * NEXP + e] + part[(128 + row) * NEXP + e] + __ldg(gb + e);
        float m = lg[0];
        #pragma unroll
        for (int e = 1; e < NEXP; e++) m = fmaxf(m, lg[e]);
        float p[NEXP], s = 0.f;
        #pragma unroll
        for (int e = 0; e < NEXP; e++) { p[e] = expf(lg[e] - m); s += p[e]; }
        const float inv = 1.f / s;
        float g[NEXP];
        #pragma unroll
        for (int e = 0; e < NEXP; e++) g[e] = p[e] * inv;

        int i1 = 0;
        #pragma unroll
        for (int e = 1; e < NEXP; e++) if (lg[e] > lg[i1]) i1 = e;
        int i2 = (i1 == 0) ? 1 : 0;
        #pragma unroll
        for (int e = 0; e < NEXP; e++) if (e != i1 && lg[e] > lg[i2]) i2 = e;

        const int a  = min(i1, i2);
        const int bb = max(i1, i2);
        const int pidx = a * 8 + bb;
        const long tok = tok0 + row;

        const int r = atomicAdd(&g_hist[pidx], 1);
        g_pr[tok]  = ((uint32_t)pidx << 24) | (uint32_t)r;
        g_g12[tok] = make_float2(g[a], g[bb]);
        g_gf[tok]  = make_uint4(packh2(g[0], g[1]), packh2(g[2], g[3]),
                                packh2(g[4], g[5]), packh2(g[6], g[7]));
    }
}

// ---------------- kernel 3: parallel scan + tile table ----------------

__global__ void scan_kernel() {
    __shared__ int sc[64], st[64];
    const int p = threadIdx.x;
    const int c  = g_hist[p];
    const int nt = (c + 127) >> 7;
    sc[p] = c; st[p] = nt;
    __syncthreads();
    #pragma unroll
    for (int d = 1; d < 64; d <<= 1) {
        int vc = 0, vt = 0;
        if (p >= d) { vc = sc[p - d]; vt = st[p - d]; }
        __syncthreads();
        sc[p] += vc; st[p] += vt;
        __syncthreads();
    }
    const int base = sc[p] - c;
    int tb = st[p] - nt;
    g_off[p] = base;
    if (p == 63) g_ntiles[0] = st[63];
    const int a = p >> 3, bb = p & 7;
    for (int s = 0; s < c; s += 128, tb++)
        g_tiles[tb] = make_int4(base + s, min(128, c - s), a, bb);
}

// ---------------- kernel 4: fill grouped token list ----------------

__global__ void fill_kernel() {
    const int tok = blockIdx.x * blockDim.x + threadIdx.x;
    const uint32_t v = g_pr[tok];
    g_tok[g_off[v >> 24] + (v & 0xFFFFFF)] = tok;
}

// ---------------- kernel 5: persistent pair-group GEMM, double-buffered ----------------

__device__ __forceinline__ void prefetch_tile(char* smem, uint32_t sb, int tid,
                                              int4 tl, int pp)
{
    const int start = tl.x, count = tl.y, ea = tl.z, eb = tl.w;
    const int row  = tid >> 2;
    const int part = tid & 3;
    const bool valid = row < count;
    int tok = 0;
    if (valid) tok = __ldg(&g_tok[start + row]);
    const uint32_t z16 = valid ? 16u : 0u;

    if (part == 0) {
        ((int*)(smem + OFF_TK + pp * 512))[row] = tok;
        CP_ASYNC8Z(sb + OFF_G12 + pp * 1024 + row * 8,
                   (const char*)&g_g12[tok], valid ? 8u : 0u);
        CP_ASYNC16Z(sb + OFF_AG + pp * 4096 + row * 32,
                    (const char*)&g_gf[tok], z16);
    }
    // x row: 4 x 16B chunks, swizzled
    {
        const char* xsrc = (const char*)g_xh + (size_t)tok * 256 + part * 64;
        const uint32_t adst = sb + OFF_A + pp * 32768 + row * 256;
        const int x7 = row & 7;
        #pragma unroll
        for (int i = 0; i < 4; i++) {
            const int c16 = part * 4 + i;
            CP_ASYNC16Z(adst + ((c16 ^ x7) << 4), xsrc + i * 16, z16);
        }
    }
    // W: Wa then Wb, 4096 chunks over 512 threads
    #pragma unroll
    for (int it = 0; it < 8; it++) {
        const int c   = tid + it * 512;
        const int e   = c >> 11;
        const int r   = (c >> 4) & 127;
        const int c16 = c & 15;
        const int esel = e ? eb : ea;
        const uint32_t dst = sb + OFF_B + pp * 65536 + e * 32768 + r * 256
                           + ((c16 ^ (r & 7)) << 4);
        const char* src = (const char*)g_Wh + ((size_t)esel << 15) + r * 256 + c16 * 16;
        CP_ASYNC16(dst, src);
    }
}

__global__ void __launch_bounds__(512, 1)
moe_main_kernel(const float* __restrict__ b,
                float* __restrict__ out)
{
    extern __shared__ char smem[];
    const uint32_t sb = smem_u32(smem);

    const int tid  = threadIdx.x;
    const int lane = tid & 31;
    const int wid  = tid >> 5;

    const int nt = __ldg(g_ntiles);

    // one-time init: BG (b^T f16) + zero AG pads (both parities)
    if (tid < DIM) {
        float bv[NEXP];
        #pragma unroll
        for (int e = 0; e < NEXP; e++) bv[e] = __ldg(b + e * DIM + tid);
        uint32_t* dst = (uint32_t*)(smem + OFF_BG + tid * 32);
        dst[0] = packh2(bv[0], bv[1]);
        dst[1] = packh2(bv[2], bv[3]);
        dst[2] = packh2(bv[4], bv[5]);
        dst[3] = packh2(bv[6], bv[7]);
        dst[4] = 0; dst[5] = 0; dst[6] = 0; dst[7] = 0;
    }
    if (tid < 256) {
        const int pr = tid >> 7, r = tid & 127;
        *(uint4*)(smem + OFF_AG + pr * 4096 + r * 32 + 16) = make_uint4(0, 0, 0, 0);
    }

    int i = blockIdx.x;
    if (i >= nt) return;

    int4 cur = __ldg(&g_tiles[i]);
    prefetch_tile(smem, sb, tid, cur, 0);
    CP_COMMIT();
    int pp = 0;

    // warp tiling: 4(m) x 4(n); warp tile 32 x 32; dual accumulators
    const int mgrp = wid >> 2;
    const int ngrp = wid & 3;
    const int arow = lane & 15;
    const int hiA  = lane >> 4;                     // A col chunk 0/1
    const int brow = ((lane >> 4) & 1) * 8 + (lane & 7);
    const int hiB  = (lane >> 3) & 1;               // B col chunk 0/1
    const int acb  = hiA * 8;                       // halves (bias MMA)
    const int xA   = arow & 7;
    const int xB   = lane & 7;

    for (; i < nt; i += gridDim.x) {
        // prefetch next tile into the other buffer
        const int nxt = i + gridDim.x;
        int4 nxtTl = make_int4(0, 0, 0, 0);
        if (nxt < nt) {
            nxtTl = __ldg(&g_tiles[nxt]);
            prefetch_tile(smem, sb, tid, nxtTl, pp ^ 1);
        }
        CP_COMMIT();
        CP_WAIT1();                 // current buffer complete
        __syncthreads();

        const int count = cur.y;

        float accA[2][4][4], accB[2][4][4];
        #pragma unroll
        for (int t2 = 0; t2 < 2; t2++)
            #pragma unroll
            for (int j = 0; j < 4; j++)
                #pragma unroll
                for (int q = 0; q < 4; q++) { accA[t2][j][q] = 0.f; accB[t2][j][q] = 0.f; }

        const uint32_t aoff = sb + OFF_A + pp * 32768;
        const uint32_t boff = sb + OFF_B + pp * 65536;
        const uint32_t baseA0 = aoff + (mgrp * 32 + arow) * 256;
        const uint32_t baseA1 = baseA0 + 16 * 256;
        const uint32_t baseP0 = boff + (ngrp * 32 + brow) * 256;
        const uint32_t baseP1 = baseP0 + 16 * 256;
        const uint32_t baseQ0 = baseP0 + 32768;
        const uint32_t baseQ1 = baseP1 + 32768;

        #pragma unroll
        for (int ks = 0; ks < 8; ks++) {
            const uint32_t ofA = (uint32_t)(((2 * ks + hiA) ^ xA) << 4);
            const uint32_t ofB = (uint32_t)(((2 * ks + hiB) ^ xB) << 4);
            uint32_t a0[4], a1[4];
            LDSM_X4(a0[0], a0[1], a0[2], a0[3], baseA0 + ofA);
            LDSM_X4(a1[0], a1[1], a1[2], a1[3], baseA1 + ofA);
            uint32_t p0, p1, p2, p3, p4, p5, p6, p7;
            LDSM_X4(p0, p1, p2, p3, baseP0 + ofB);
            LDSM_X4(p4, p5, p6, p7, baseP1 + ofB);
            MMA_16816(accA[0][0], a0[0], a0[1], a0[2], a0[3], p0, p1);
            MMA_16816(accA[0][1], a0[0], a0[1], a0[2], a0[3], p2, p3);
            MMA_16816(accA[0][2], a0[0], a0[1], a0[2], a0[3], p4, p5);
            MMA_16816(accA[0][3], a0[0], a0[1], a0[2], a0[3], p6, p7);
            MMA_16816(accA[1][0], a1[0], a1[1], a1[2], a1[3], p0, p1);
            MMA_16816(accA[1][1], a1[0], a1[1], a1[2], a1[3], p2, p3);
            MMA_16816(accA[1][2], a1[0], a1[1], a1[2], a1[3], p4, p5);
            MMA_16816(accA[1][3], a1[0], a1[1], a1[2], a1[3], p6, p7);
            uint32_t q0, q1, q2, q3, q4, q5, q6, q7;
            LDSM_X4(q0, q1, q2, q3, baseQ0 + ofB);
            LDSM_X4(q4, q5, q6, q7, baseQ1 + ofB);
            MMA_16816(accB[0][0], a0[0], a0[1], a0[2], a0[3], q0, q1);
            MMA_16816(accB[0][1], a0[0], a0[1], a0[2], a0[3], q2, q3);
            MMA_16816(accB[0][2], a0[0], a0[1], a0[2], a0[3], q4, q5);
            MMA_16816(accB[0][3], a0[0], a0[1], a0[2], a0[3], q6, q7);
            MMA_16816(accB[1][0], a1[0], a1[1], a1[2], a1[3], q0, q1);
            MMA_16816(accB[1][1], a1[0], a1[1], a1[2], a1[3], q2, q3);
            MMA_16816(accB[1][2], a1[0], a1[1], a1[2], a1[3], q4, q5);
            MMA_16816(accB[1][3], a1[0], a1[1], a1[2], a1[3], q6, q7);
        }

        // combine accA = ga*accA + gb*accB
        {
            const float2* g12s = (const float2*)(smem + OFF_G12 + pp * 1024);
            #pragma unroll
            for (int t2 = 0; t2 < 2; t2++) {
                const int rlo = mgrp * 32 + t2 * 16 + (lane >> 2);
                const float2 glo = g12s[rlo];
                const float2 ghi = g12s[rlo + 8];
                #pragma unroll
                for (int j = 0; j < 4; j++) {
                    accA[t2][j][0] = glo.x * accA[t2][j][0] + glo.y * accB[t2][j][0];
                    accA[t2][j][1] = glo.x * accA[t2][j][1] + glo.y * accB[t2][j][1];
                    accA[t2][j][2] = ghi.x * accA[t2][j][2] + ghi.y * accB[t2][j][2];
                    accA[t2][j][3] = ghi.x * accA[t2][j][3] + ghi.y * accB[t2][j][3];
                }
            }
        }

        // bias MMA: accA += gates_full @ b^T
        {
            uint32_t b0, b1, b2, b3, b4, b5, b6, b7;
            LDSM_X4(b0, b1, b2, b3,
                    sb + OFF_BG + (uint32_t)((ngrp * 32 + brow) * 32 + hiB * 16));
            LDSM_X4(b4, b5, b6, b7,
                    sb + OFF_BG + (uint32_t)((ngrp * 32 + 16 + brow) * 32 + hiB * 16));
            const uint32_t agb = sb + OFF_AG + pp * 4096;
            #pragma unroll
            for (int t2 = 0; t2 < 2; t2++) {
                uint32_t a0, a1, a2, a3;
                LDSM_X4(a0, a1, a2, a3,
                        agb + (uint32_t)((mgrp * 32 + t2 * 16 + arow) * 32 + acb * 2));
                MMA_16816(accA[t2][0], a0, a1, a2, a3, b0, b1);
                MMA_16816(accA[t2][1], a0, a1, a2, a3, b2, b3);
                MMA_16816(accA[t2][2], a0, a1, a2, a3, b4, b5);
                MMA_16816(accA[t2][3], a0, a1, a2, a3, b6, b7);
            }
        }

        // scatter stores (sector-perfect: 4 lanes x 8B = one 32B sector)
        {
            const int* stok = (const int*)(smem + OFF_TK + pp * 512);
            #pragma unroll
            for (int t2 = 0; t2 < 2; t2++) {
                const int lr = mgrp * 32 + t2 * 16 + (lane >> 2);
                const bool ok0 = lr < count;
                const bool ok1 = (lr + 8) < count;
                const long tk0 = ok0 ? stok[lr] : 0;
                const long tk1 = ok1 ? stok[lr + 8] : 0;
                #pragma unroll
                for (int j = 0; j < 4; j++) {
                    const int col = ngrp * 32 + j * 8 + (lane & 3) * 2;
                    if (ok0) *(float2*)(out + tk0 * DIM + col) =
                        make_float2(accA[t2][j][0], accA[t2][j][1]);
                    if (ok1) *(float2*)(out + tk1 * DIM + col) =
                        make_float2(accA[t2][j][2], accA[t2][j][3]);
                }
            }
        }

        __syncthreads();       // buffer pp free for reuse
        cur = nxtTl;
        pp ^= 1;
    }
}

// ---------------- launch ----------------

extern "C" void kernel_launch(void* const* d_in, const int* in_sizes, int n_in,
                              void* d_out, int out_size)
{
    const float* x  = (const float*)d_in[0];
    const float* gW = (const float*)d_in[1];
    const float* gb = (const float*)d_in[2];
    const float* W  = (const float*)d_in[3];
    const float* b  = (const float*)d_in[4];
    float* out = (float*)d_out;

    int sms = 148;
    cudaDeviceGetAttribute(&sms, cudaDevAttrMultiProcessorCount, 0);

    convert_w_kernel<<<NEXP * DIM * DIM / 4 / 256, 256>>>(W);
    routing_kernel<<<NTOK / 128, 256>>>(x, gW, gb);
    scan_kernel<<<1, 64>>>();
    fill_kernel<<<NTOK / 256, 256>>>();

    cudaFuncSetAttribute(moe_main_kernel,
                         cudaFuncAttributeMaxDynamicSharedMemorySize, SMEM_MAIN);
    moe_main_kernel<<<sms, 512, SMEM_MAIN>>>(b, out);
}

// round 8
// speedup vs baseline: 2.0211x; 1.0360x over previous
#include <cuda_runtime.h>
#include <cuda_fp16.h>
#include <cstdint>

// ---------------- PTX helpers (family-agnostic: sm_80-level) ----------------

__device__ __forceinline__ uint32_t smem_u32(const void* p) {
    uint32_t a;
    asm("{ .reg .u64 t; cvta.to.shared.u64 t, %1; cvt.u32.u64 %0, t; }" : "=r"(a) : "l"(p));
    return a;
}

#define LDSM_X4(r0,r1,r2,r3,addr) \
    asm volatile("ldmatrix.sync.aligned.m8n8.x4.shared.b16 {%0,%1,%2,%3}, [%4];" \
        : "=r"(r0),"=r"(r1),"=r"(r2),"=r"(r3) : "r"(addr))

#define MMA_16816(c,a0,a1,a2,a3,b0,b1) \
    asm volatile("mma.sync.aligned.m16n8k16.row.col.f32.f16.f16.f32 " \
        "{%0,%1,%2,%3}, {%4,%5,%6,%7}, {%8,%9}, {%0,%1,%2,%3};" \
        : "+f"((c)[0]),"+f"((c)[1]),"+f"((c)[2]),"+f"((c)[3]) \
        : "r"(a0),"r"(a1),"r"(a2),"r"(a3),"r"(b0),"r"(b1))

#define CP_ASYNC16(dst,src) \
    asm volatile("cp.async.cg.shared.global [%0], [%1], 16;" :: "r"(dst),"l"(src) : "memory")
#define CP_ASYNC16Z(dst,src,sz) \
    asm volatile("cp.async.cg.shared.global [%0], [%1], 16, %2;" :: "r"(dst),"l"(src),"r"(sz) : "memory")
#define CP_ASYNC8Z(dst,src,sz) \
    asm volatile("cp.async.ca.shared.global [%0], [%1], 8, %2;" :: "r"(dst),"l"(src),"r"(sz) : "memory")
#define CP_COMMIT() asm volatile("cp.async.commit_group;" ::: "memory")
#define CP_WAIT1()  asm volatile("cp.async.wait_group 1;" ::: "memory")

__device__ __forceinline__ uint32_t packh2(float a, float b) {
    return (uint32_t)__half_as_ushort(__float2half_rn(a)) |
           ((uint32_t)__half_as_ushort(__float2half_rn(b)) << 16);
}

// ---------------- problem constants ----------------

static constexpr int DIM   = 128;
static constexpr int NEXP  = 8;
static constexpr int NTOK  = 524288;
static constexpr int MAX_TILES = 4160;

// main-kernel smem layout (bytes); A/B rows are 256B, XOR-swizzled 16B chunks
static constexpr int OFF_A   = 0;        // 2 x 32768  (x f16, 128 rows x 256B)
static constexpr int OFF_B   = 65536;    // 65536      (Wa 32KB + Wb 32KB, persistent)
static constexpr int OFF_AG  = 131072;   // 2 x 4096   (full gates f16, 32B rows, k-pad)
static constexpr int OFF_G12 = 139264;   // 2 x 1024   (ga,gb fp32)
static constexpr int OFF_TK  = 141312;   // 2 x 512    (token ids)
static constexpr int OFF_BG  = 142336;   // 4096       (b^T f16, 32B rows, k-pad)
static constexpr int SMEM_MAIN = 146432;

// ---------------- device scratch (static: no allocations) ----------------

__device__ __align__(16) unsigned char g_Wh[NEXP * DIM * DIM * 2];   // W in f16
__device__ __align__(16) unsigned char g_xh[(size_t)NTOK * DIM * 2]; // x in f16 (128 MB)
__device__ int    g_hist[64];
__device__ int    g_off[64];
__device__ int    g_ntiles[1];
__device__ int4   g_tiles[MAX_TILES];    // (start, count, e_a, e_b)
__device__ uint32_t g_pr[NTOK];          // pair<<24 | rank
__device__ float2   g_g12[NTOK];         // (g_a, g_b)
__device__ uint4    g_gf[NTOK];          // 8 gates as f16
__device__ int      g_tok[NTOK];         // grouped token ids

// ---------------- kernel 1: W fp32 -> f16 (+ zero hist) ----------------

__global__ void convert_w_kernel(const float* __restrict__ W) {
    if (blockIdx.x == 0 && threadIdx.x < 64) g_hist[threadIdx.x] = 0;
    int i = blockIdx.x * blockDim.x + threadIdx.x;     // 32768 float4s
    float4 v = ((const float4*)W)[i];
    ((uint2*)g_Wh)[i] = make_uint2(packh2(v.x, v.y), packh2(v.z, v.w));
}

// ---------------- kernel 2: routing (gating + softmax + top-2 + x->f16) ----------------

__global__ void __launch_bounds__(256, 2)
routing_kernel(const float* __restrict__ x,
               const float* __restrict__ gW,
               const float* __restrict__ gb)
{
    __shared__ float gws[NEXP * DIM];          // 4 KB
    __shared__ float part[256 * NEXP];         // 8 KB
    __shared__ char  xstage[128 * 256];        // 32 KB (f16 rows, swizzled chunks)

    const int tid  = threadIdx.x;
    const int row  = tid & 127;
    const int half = tid >> 7;
    const long tok0 = (long)blockIdx.x * 128;

    ((float4*)gws)[tid] = ((const float4*)gW)[tid];

    float4 xv[16];
    {
        const float4* xg = (const float4*)(x + (tok0 + row) * DIM + half * 64);
        #pragma unroll
        for (int i = 0; i < 16; i++) xv[i] = __ldg(xg + i);
    }

    // stage f16 row halves into swizzled xstage
    {
        const int x7 = row & 7;
        #pragma unroll
        for (int j = 0; j < 8; j++) {
            uint4 u = make_uint4(packh2(xv[2*j].x,   xv[2*j].y),
                                 packh2(xv[2*j].z,   xv[2*j].w),
                                 packh2(xv[2*j+1].x, xv[2*j+1].y),
                                 packh2(xv[2*j+1].z, xv[2*j+1].w));
            const int c16 = half * 8 + j;
            *(uint4*)(xstage + row * 256 + ((c16 ^ x7) << 4)) = u;
        }
    }
    __syncthreads();

    // coalesced xh store (reads de-swizzled)
    {
        uint4* xg = (uint4*)(g_xh + (size_t)tok0 * 256);
        #pragma unroll
        for (int it = 0; it < 8; it++) {
            const int j  = tid + it * 256;       // 2048 chunks
            const int r  = j >> 4;
            const int c16 = j & 15;
            xg[j] = *(const uint4*)(xstage + r * 256 + ((c16 ^ (r & 7)) << 4));
        }
    }

    // gating partial dots
    #pragma unroll
    for (int e = 0; e < NEXP; e++) {
        const float4* ge = (const float4*)(gws + e * DIM) + half * 16;
        float s = 0.f;
        #pragma unroll
        for (int i = 0; i < 16; i++) {
            float4 g4 = ge[i];
            s += xv[i].x * g4.x + xv[i].y * g4.y + xv[i].z * g4.z + xv[i].w * g4.w;
        }
        part[(half * 128 + row) * NEXP + e] = s;
    }
    __syncthreads();

    if (half == 0) {
        float lg[NEXP];
        #pragma unroll
        for (int e = 0; e < NEXP; e++)
            lg[e] = part[row * NEXP + e] + part[(128 + row) * NEXP + e] + __ldg(gb + e);
        float m = lg[0];
        #pragma unroll
        for (int e = 1; e < NEXP; e++) m = fmaxf(m, lg[e]);
        float p[NEXP], s = 0.f;
        #pragma unroll
        for (int e = 0; e < NEXP; e++) { p[e] = expf(lg[e] - m); s += p[e]; }
        const float inv = 1.f / s;
        float g[NEXP];
        #pragma unroll
        for (int e = 0; e < NEXP; e++) g[e] = p[e] * inv;

        int i1 = 0;
        #pragma unroll
        for (int e = 1; e < NEXP; e++) if (lg[e] > lg[i1]) i1 = e;
        int i2 = (i1 == 0) ? 1 : 0;
        #pragma unroll
        for (int e = 0; e < NEXP; e++) if (e != i1 && lg[e] > lg[i2]) i2 = e;

        const int a  = min(i1, i2);
        const int bb = max(i1, i2);
        const int pidx = a * 8 + bb;
        const long tok = tok0 + row;

        const int r = atomicAdd(&g_hist[pidx], 1);
        g_pr[tok]  = ((uint32_t)pidx << 24) | (uint32_t)r;
        g_g12[tok] = make_float2(g[a], g[bb]);
        g_gf[tok]  = make_uint4(packh2(g[0], g[1]), packh2(g[2], g[3]),
                                packh2(g[4], g[5]), packh2(g[6], g[7]));
    }
}

// ---------------- kernel 3: parallel scan + tile table ----------------

__global__ void scan_kernel() {
    __shared__ int sc[64], st[64];
    const int p = threadIdx.x;
    const int c  = g_hist[p];
    const int nt = (c + 127) >> 7;
    sc[p] = c; st[p] = nt;
    __syncthreads();
    #pragma unroll
    for (int d = 1; d < 64; d <<= 1) {
        int vc = 0, vt = 0;
        if (p >= d) { vc = sc[p - d]; vt = st[p - d]; }
        __syncthreads();
        sc[p] += vc; st[p] += vt;
        __syncthreads();
    }
    const int base = sc[p] - c;
    int tb = st[p] - nt;
    g_off[p] = base;
    if (p == 63) g_ntiles[0] = st[63];
    const int a = p >> 3, bb = p & 7;
    for (int s = 0; s < c; s += 128, tb++)
        g_tiles[tb] = make_int4(base + s, min(128, c - s), a, bb);
}

// ---------------- kernel 4: fill grouped token list ----------------

__global__ void fill_kernel() {
    const int tok = blockIdx.x * blockDim.x + threadIdx.x;
    const uint32_t v = g_pr[tok];
    g_tok[g_off[v >> 24] + (v & 0xFFFFFF)] = tok;
}

// ---------------- kernel 5: persistent pair-group GEMM ----------------
// Chunked tile assignment: consecutive tiles share the expert pair, so W
// stays resident in smem; only A/gates are double-buffered per tile.

__device__ __forceinline__ void prefetch_A(char* smem, uint32_t sb, int tid,
                                           int4 tl, int pp)
{
    const int start = tl.x, count = tl.y;
    const int row  = tid >> 2;
    const int part = tid & 3;
    const bool valid = row < count;
    int tok = 0;
    if (valid) tok = __ldg(&g_tok[start + row]);
    const uint32_t z16 = valid ? 16u : 0u;

    if (part == 0) {
        ((int*)(smem + OFF_TK + pp * 512))[row] = tok;
        CP_ASYNC8Z(sb + OFF_G12 + pp * 1024 + row * 8,
                   (const char*)&g_g12[tok], valid ? 8u : 0u);
        CP_ASYNC16Z(sb + OFF_AG + pp * 4096 + row * 32,
                    (const char*)&g_gf[tok], z16);
    }
    const char* xsrc = (const char*)g_xh + (size_t)tok * 256 + part * 64;
    const uint32_t adst = sb + OFF_A + pp * 32768 + row * 256;
    const int x7 = row & 7;
    #pragma unroll
    for (int i = 0; i < 4; i++) {
        const int c16 = part * 4 + i;
        CP_ASYNC16Z(adst + ((c16 ^ x7) << 4), xsrc + i * 16, z16);
    }
}

__device__ __forceinline__ void load_W(uint32_t sb, int tid, int ea, int eb)
{
    #pragma unroll
    for (int it = 0; it < 8; it++) {
        const int c   = tid + it * 512;          // 4096 16B chunks
        const int e   = c >> 11;
        const int r   = (c >> 4) & 127;
        const int c16 = c & 15;
        const int esel = e ? eb : ea;
        const uint32_t dst = sb + OFF_B + e * 32768 + r * 256 + ((c16 ^ (r & 7)) << 4);
        const char* src = (const char*)g_Wh + ((size_t)esel << 15) + r * 256 + c16 * 16;
        CP_ASYNC16(dst, src);
    }
}

__global__ void __launch_bounds__(512, 1)
moe_main_kernel(const float* __restrict__ b,
                float* __restrict__ out)
{
    extern __shared__ char smem[];
    const uint32_t sb = smem_u32(smem);

    const int tid  = threadIdx.x;
    const int lane = tid & 31;
    const int wid  = tid >> 5;

    const int nt = __ldg(g_ntiles);
    const int chunk = (nt + gridDim.x - 1) / gridDim.x;
    const int c0 = blockIdx.x * chunk;
    const int c1 = min(c0 + chunk, nt);
    if (c0 >= c1) return;

    // one-time init: BG (b^T f16) + zero AG pads (both parities)
    if (tid < DIM) {
        float bv[NEXP];
        #pragma unroll
        for (int e = 0; e < NEXP; e++) bv[e] = __ldg(b + e * DIM + tid);
        uint32_t* dst = (uint32_t*)(smem + OFF_BG + tid * 32);
        dst[0] = packh2(bv[0], bv[1]);
        dst[1] = packh2(bv[2], bv[3]);
        dst[2] = packh2(bv[4], bv[5]);
        dst[3] = packh2(bv[6], bv[7]);
        dst[4] = 0; dst[5] = 0; dst[6] = 0; dst[7] = 0;
    }
    if (tid < 256) {
        const int pr = tid >> 7, r = tid & 127;
        *(uint4*)(smem + OFF_AG + pr * 4096 + r * 32 + 16) = make_uint4(0, 0, 0, 0);
    }

    int4 cur = __ldg(&g_tiles[c0]);
    prefetch_A(smem, sb, tid, cur, 0);
    CP_COMMIT();                                 // group: A(c0)
    load_W(sb, tid, cur.z, cur.w);
    CP_COMMIT();                                 // group: W(c0)
    int pp = 0;

    // warp tiling: 4(m) x 4(n); warp tile 32 x 32; dual accumulators
    const int mgrp = wid >> 2;
    const int ngrp = wid & 3;
    const int arow = lane & 15;
    const int hiA  = lane >> 4;
    const int brow = ((lane >> 4) & 1) * 8 + (lane & 7);
    const int hiB  = (lane >> 3) & 1;
    const int acb  = hiA * 8;
    const int xA   = arow & 7;
    const int xB   = lane & 7;

    for (int i = c0; i < c1; i++, pp ^= 1) {
        int4 nxtTl = make_int4(0, 0, cur.z, cur.w);
        if (i + 1 < c1) {
            nxtTl = __ldg(&g_tiles[i + 1]);
            prefetch_A(smem, sb, tid, nxtTl, pp ^ 1);
        }
        CP_COMMIT();                             // group: A(i+1) (possibly empty)
        CP_WAIT1();                              // A(i) (+ W if reloaded) done
        __syncthreads();

        const int count = cur.y;

        float accA[2][4][4], accB[2][4][4];
        #pragma unroll
        for (int t2 = 0; t2 < 2; t2++)
            #pragma unroll
            for (int j = 0; j < 4; j++)
                #pragma unroll
                for (int q = 0; q < 4; q++) { accA[t2][j][q] = 0.f; accB[t2][j][q] = 0.f; }

        const uint32_t aoff = sb + OFF_A + pp * 32768;
        const uint32_t baseA0 = aoff + (mgrp * 32 + arow) * 256;
        const uint32_t baseA1 = baseA0 + 16 * 256;
        const uint32_t baseP0 = sb + OFF_B + (ngrp * 32 + brow) * 256;
        const uint32_t baseP1 = baseP0 + 16 * 256;
        const uint32_t baseQ0 = baseP0 + 32768;
        const uint32_t baseQ1 = baseP1 + 32768;

        #pragma unroll
        for (int ks = 0; ks < 8; ks++) {
            const uint32_t ofA = (uint32_t)(((2 * ks + hiA) ^ xA) << 4);
            const uint32_t ofB = (uint32_t)(((2 * ks + hiB) ^ xB) << 4);
            uint32_t a0[4], a1[4];
            LDSM_X4(a0[0], a0[1], a0[2], a0[3], baseA0 + ofA);
            LDSM_X4(a1[0], a1[1], a1[2], a1[3], baseA1 + ofA);
            uint32_t p0, p1, p2, p3, p4, p5, p6, p7;
            LDSM_X4(p0, p1, p2, p3, baseP0 + ofB);
            LDSM_X4(p4, p5, p6, p7, baseP1 + ofB);
            MMA_16816(accA[0][0], a0[0], a0[1], a0[2], a0[3], p0, p1);
            MMA_16816(accA[0][1], a0[0], a0[1], a0[2], a0[3], p2, p3);
            MMA_16816(accA[0][2], a0[0], a0[1], a0[2], a0[3], p4, p5);
            MMA_16816(accA[0][3], a0[0], a0[1], a0[2], a0[3], p6, p7);
            MMA_16816(accA[1][0], a1[0], a1[1], a1[2], a1[3], p0, p1);
            MMA_16816(accA[1][1], a1[0], a1[1], a1[2], a1[3], p2, p3);
            MMA_16816(accA[1][2], a1[0], a1[1], a1[2], a1[3], p4, p5);
            MMA_16816(accA[1][3], a1[0], a1[1], a1[2], a1[3], p6, p7);
            uint32_t q0, q1, q2, q3, q4, q5, q6, q7;
            LDSM_X4(q0, q1, q2, q3, baseQ0 + ofB);
            LDSM_X4(q4, q5, q6, q7, baseQ1 + ofB);
            MMA_16816(accB[0][0], a0[0], a0[1], a0[2], a0[3], q0, q1);
            MMA_16816(accB[0][1], a0[0], a0[1], a0[2], a0[3], q2, q3);
            MMA_16816(accB[0][2], a0[0], a0[1], a0[2], a0[3], q4, q5);
            MMA_16816(accB[0][3], a0[0], a0[1], a0[2], a0[3], q6, q7);
            MMA_16816(accB[1][0], a1[0], a1[1], a1[2], a1[3], q0, q1);
            MMA_16816(accB[1][1], a1[0], a1[1], a1[2], a1[3], q2, q3);
            MMA_16816(accB[1][2], a1[0], a1[1], a1[2], a1[3], q4, q5);
            MMA_16816(accB[1][3], a1[0], a1[1], a1[2], a1[3], q6, q7);
        }

        // combine accA = ga*accA + gb*accB
        {
            const float2* g12s = (const float2*)(smem + OFF_G12 + pp * 1024);
            #pragma unroll
            for (int t2 = 0; t2 < 2; t2++) {
                const int rlo = mgrp * 32 + t2 * 16 + (lane >> 2);
                const float2 glo = g12s[rlo];
                const float2 ghi = g12s[rlo + 8];
                #pragma unroll
                for (int j = 0; j < 4; j++) {
                    accA[t2][j][0] = glo.x * accA[t2][j][0] + glo.y * accB[t2][j][0];
                    accA[t2][j][1] = glo.x * accA[t2][j][1] + glo.y * accB[t2][j][1];
                    accA[t2][j][2] = ghi.x * accA[t2][j][2] + ghi.y * accB[t2][j][2];
                    accA[t2][j][3] = ghi.x * accA[t2][j][3] + ghi.y * accB[t2][j][3];
                }
            }
        }

        // bias MMA: accA += gates_full @ b^T
        {
            uint32_t b0, b1, b2, b3, b4, b5, b6, b7;
            LDSM_X4(b0, b1, b2, b3,
                    sb + OFF_BG + (uint32_t)((ngrp * 32 + brow) * 32 + hiB * 16));
            LDSM_X4(b4, b5, b6, b7,
                    sb + OFF_BG + (uint32_t)((ngrp * 32 + 16 + brow) * 32 + hiB * 16));
            const uint32_t agb = sb + OFF_AG + pp * 4096;
            #pragma unroll
            for (int t2 = 0; t2 < 2; t2++) {
                uint32_t a0, a1, a2, a3;
                LDSM_X4(a0, a1, a2, a3,
                        agb + (uint32_t)((mgrp * 32 + t2 * 16 + arow) * 32 + acb * 2));
                MMA_16816(accA[t2][0], a0, a1, a2, a3, b0, b1);
                MMA_16816(accA[t2][1], a0, a1, a2, a3, b2, b3);
                MMA_16816(accA[t2][2], a0, a1, a2, a3, b4, b5);
                MMA_16816(accA[t2][3], a0, a1, a2, a3, b6, b7);
            }
        }

        // scatter stores (sector-perfect: 4 lanes x 8B = one 32B sector)
        {
            const int* stok = (const int*)(smem + OFF_TK + pp * 512);
            #pragma unroll
            for (int t2 = 0; t2 < 2; t2++) {
                const int lr = mgrp * 32 + t2 * 16 + (lane >> 2);
                const bool ok0 = lr < count;
                const bool ok1 = (lr + 8) < count;
                const long tk0 = ok0 ? stok[lr] : 0;
                const long tk1 = ok1 ? stok[lr + 8] : 0;
                #pragma unroll
                for (int j = 0; j < 4; j++) {
                    const int col = ngrp * 32 + j * 8 + (lane & 3) * 2;
                    if (ok0) *(float2*)(out + tk0 * DIM + col) =
                        make_float2(accA[t2][j][0], accA[t2][j][1]);
                    if (ok1) *(float2*)(out + tk1 * DIM + col) =
                        make_float2(accA[t2][j][2], accA[t2][j][3]);
                }
            }
        }

        __syncthreads();       // A[pp] free; W reads done (needed before W reload)

        // W reload for next tile if the expert pair changes (rare)
        if (i + 1 < c1 && (nxtTl.z != cur.z || nxtTl.w != cur.w)) {
            load_W(sb, tid, nxtTl.z, nxtTl.w);
            CP_COMMIT();                        // group: W(i+1)
        }
        cur = nxtTl;
    }
}

// ---------------- launch ----------------

extern "C" void kernel_launch(void* const* d_in, const int* in_sizes, int n_in,
                              void* d_out, int out_size)
{
    const float* x  = (const float*)d_in[0];
    const float* gW = (const float*)d_in[1];
    const float* gb = (const float*)d_in[2];
    const float* W  = (const float*)d_in[3];
    const float* b  = (const float*)d_in[4];
    float* out = (float*)d_out;

    int sms = 148;
    cudaDeviceGetAttribute(&sms, cudaDevAttrMultiProcessorCount, 0);

    convert_w_kernel<<<NEXP * DIM * DIM / 4 / 256, 256>>>(W);
    routing_kernel<<<NTOK / 128, 256>>>(x, gW, gb);
    scan_kernel<<<1, 64>>>();
    fill_kernel<<<NTOK / 256, 256>>>();

    cudaFuncSetAttribute(moe_main_kernel,
                         cudaFuncAttributeMaxDynamicSharedMemorySize, SMEM_MAIN);
    moe_main_kernel<<<sms, 512, SMEM_MAIN>>>(b, out);
}